// round 11
// baseline (speedup 1.0000x reference)
#include <cuda_runtime.h>
#include <cuda_bf16.h>

// MX quantize-dequantize: block size 32, E8M0 shared scale, E4M3 elements.
// v7: Blackwell 256-bit global accesses. One ld.global.v8.f32 + one
// st.global.v8.f32 per thread (8 elements). Warp touches one contiguous
// 1KB window per memory instruction. Lane l holds elements 8l..8l+7, so
// 4 consecutive lanes span one 32-element MX block -> amax via two
// shfl.xor (1, 2). No cache hints (proven neutral). Exact pow2
// bit-constructed scale math throughout.

__device__ __forceinline__ float mx_qdq_elem(float v, float inv_scale, float scale) {
    unsigned sbit = __float_as_uint(v) & 0x80000000u;
    float mag = fabsf(v) * inv_scale;          // exact pow2 multiply
    mag = fminf(mag, 448.0f);                  // E4M3 saturate
    float safe = fmaxf(mag, 0.015625f);        // 2^-6 (subnormal region -> emin)
    int e = (int)(__float_as_uint(safe) >> 23) - 127;
    float quantum = __uint_as_float((unsigned)((e - 3) + 127) << 23); // 2^(e-3)
    float invq    = __uint_as_float((unsigned)((3 - e) + 127) << 23); // 2^(3-e)
    float q = rintf(mag * invq) * quantum * scale; // round-half-even, dequant
    return __uint_as_float(__float_as_uint(q) | sbit);
}

__device__ __forceinline__ void ldg256(const float* __restrict__ p, float* v) {
    asm volatile(
        "ld.global.v8.f32 {%0,%1,%2,%3,%4,%5,%6,%7}, [%8];"
        : "=f"(v[0]), "=f"(v[1]), "=f"(v[2]), "=f"(v[3]),
          "=f"(v[4]), "=f"(v[5]), "=f"(v[6]), "=f"(v[7])
        : "l"(p));
}

__device__ __forceinline__ void stg256(float* __restrict__ p, const float* v) {
    asm volatile(
        "st.global.v8.f32 [%0], {%1,%2,%3,%4,%5,%6,%7,%8};"
        :: "l"(p),
           "f"(v[0]), "f"(v[1]), "f"(v[2]), "f"(v[3]),
           "f"(v[4]), "f"(v[5]), "f"(v[6]), "f"(v[7])
        : "memory");
}

__global__ void __launch_bounds__(256)
mx_qdq_kernel(const float* __restrict__ x, float* __restrict__ y, int n) {
    int t  = blockIdx.x * blockDim.x + threadIdx.x;
    long long base = (long long)t * 8;          // 8 contiguous elements/thread
    if (base + 7 >= n) return;

    float v[8];
    ldg256(x + base, v);

    // per-thread amax over 8 elements
    float m = fmaxf(fmaxf(fmaxf(fabsf(v[0]), fabsf(v[1])),
                          fmaxf(fabsf(v[2]), fabsf(v[3]))),
                    fmaxf(fmaxf(fabsf(v[4]), fabsf(v[5])),
                          fmaxf(fabsf(v[6]), fabsf(v[7]))));

    // reduce across the 4 lanes sharing this 32-element MX block
    m = fmaxf(m, __shfl_xor_sync(0xffffffffu, m, 1));
    m = fmaxf(m, __shfl_xor_sync(0xffffffffu, m, 2));

    // shared_exp = floor(log2(amax)) - 8, exact via exponent-field extract;
    // clamp keeps the bit-constructed pow2 floats normal. amax==0 -> all
    // elements are zero -> scale value irrelevant.
    int se = ((int)(__float_as_uint(m) >> 23) - 127) - 8;
    se = max(se, -126);
    float scale     = __uint_as_float((unsigned)(se + 127) << 23);
    float inv_scale = __uint_as_float((unsigned)(127 - se) << 23);

    float o[8];
#pragma unroll
    for (int k = 0; k < 8; k++)
        o[k] = mx_qdq_elem(v[k], inv_scale, scale);

    stg256(y + base, o);
}

extern "C" void kernel_launch(void* const* d_in, const int* in_sizes, int n_in,
                              void* d_out, int out_size) {
    const float* x = (const float*)d_in[0];
    float*       y = (float*)d_out;
    int n = in_sizes[0];           // 33,554,432 (divisible by 32)
    int nthreads = n / 8;          // 8 elements per thread -> 4,194,304 threads
    int block = 256;
    int grid  = (nthreads + block - 1) / block;  // 16384
    mx_qdq_kernel<<<grid, block>>>(x, y, n);
}